// round 6
// baseline (speedup 1.0000x reference)
#include <cuda_runtime.h>
#include <cuda_fp16.h>
#include <math.h>

#define F_IN 128
#define HC1 128     // heads*hidden = 8*16
#define H1 8
#define F_OUT 64
#define MAXN 100000
#define MAXDEG 128
#define REC1_STRIDE 288   // 256B fp16 features + 32B prescaled logits
#define REC2_STRIDE 144   // 128B fp16 features + 4B prescaled logit (+pad)
#define LOG2E 1.4426950408889634f

// ---------------- scratch (static device globals; no dynamic alloc) --------
__device__ __align__(16) unsigned char g_rec1[(size_t)MAXN * REC1_STRIDE];
__device__ __align__(16) unsigned char g_rec2[(size_t)MAXN * REC2_STRIDE];
__device__ float  g_h[(size_t)MAXN * HC1];     // layer-1 out [N,128] fp32
__device__ float  g_ad1[MAXN * H1];            // prescaled dst logits, layer1
__device__ float  g_ad2[MAXN];                 // prescaled dst logit,  layer2
__device__ int    g_deg[MAXN];
__device__ int    g_adj[MAXN * MAXDEG];

__device__ __forceinline__ float ex2(float x) {
    float r; asm("ex2.approx.f32 %0, %1;" : "=f"(r) : "f"(x)); return r;
}
// weight from prescaled logit sum t: exp(lrelu(t/log2e)) == ex2(max(t, 0.2t))
__device__ __forceinline__ float wfun(float t) { return ex2(fmaxf(t, 0.2f * t)); }

__device__ __forceinline__ void acc4h(float4& acc, float w, uint2 q) {
    float2 f0 = __half22float2(*reinterpret_cast<half2*>(&q.x));
    float2 f1 = __half22float2(*reinterpret_cast<half2*>(&q.y));
    acc.x += w * f0.x; acc.y += w * f0.y;
    acc.z += w * f1.x; acc.w += w * f1.y;
}

// ---------------- adjacency build ------------------------------------------
__global__ void k_zero(int N) {
    int i = blockIdx.x * blockDim.x + threadIdx.x;
    if (i < N) g_deg[i] = 0;
}

__global__ void k_scatter(const int* __restrict__ ei, int E) {
    int t = blockIdx.x * blockDim.x + threadIdx.x;
    int e0 = t * 4;
    if (e0 >= E) return;
    int4 s = *(const int4*)(ei + e0);
    int4 d = *(const int4*)(ei + E + e0);
    int p;
    p = atomicAdd(&g_deg[d.x], 1); if (p < MAXDEG) g_adj[(d.x << 7) + p] = s.x;
    p = atomicAdd(&g_deg[d.y], 1); if (p < MAXDEG) g_adj[(d.y << 7) + p] = s.y;
    p = atomicAdd(&g_deg[d.z], 1); if (p < MAXDEG) g_adj[(d.z << 7) + p] = s.z;
    p = atomicAdd(&g_deg[d.w], 1); if (p < MAXDEG) g_adj[(d.w << 7) + p] = s.w;
}

// ---------------- double-buffered SGEMM with fused epilogue -----------------
// C[M,BN] = A[M,128] @ B[128,BN]; epilogue: fp16 features + prescaled logits
// into packed records; dst logits into o_ad.
template <int BN, int TN, bool ELU, bool L1>
__global__ __launch_bounds__(256) void k_sgemm(const float* __restrict__ A,
                                               const float* __restrict__ B,
                                               unsigned char* __restrict__ rec,
                                               const float* __restrict__ att_s,
                                               const float* __restrict__ att_d,
                                               float* __restrict__ o_ad,
                                               int M) {
    constexpr int BM = 128, BK = 16, TM = 8;
    constexpr int NSTEP = F_IN / BK;          // 8
    constexpr int BROWS = 1024 / BN;          // B k-rows per load pass
    constexpr int NB = BK / BROWS;            // float4 B loads per thread
    __shared__ float As[2][BK][BM];
    __shared__ float Bs[2][BK][BN];
    const int tid = threadIdx.x;
    const int tx = tid % (BN / TN);
    const int ty = tid / (BN / TN);
    const int m0 = blockIdx.x * BM;
    const int ar = tid >> 2, ac = (tid & 3) * 4;
    const int br = tid / (BN / 4), bc = (tid % (BN / 4)) * 4;

    float acc[TM][TN];
#pragma unroll
    for (int i = 0; i < TM; i++)
#pragma unroll
        for (int j = 0; j < TN; j++) acc[i][j] = 0.f;

    float4 pa[2], pb[NB];

    auto loadAB = [&](int k0) {
#pragma unroll
        for (int i = 0; i < 2; i++) {
            int row = m0 + ar + i * 64;
            float4 v = make_float4(0.f, 0.f, 0.f, 0.f);
            if (row < M) v = *(const float4*)(A + (long long)row * F_IN + k0 + ac);
            if (ELU) {
                v.x = v.x > 0.f ? v.x : expm1f(v.x);
                v.y = v.y > 0.f ? v.y : expm1f(v.y);
                v.z = v.z > 0.f ? v.z : expm1f(v.z);
                v.w = v.w > 0.f ? v.w : expm1f(v.w);
            }
            pa[i] = v;
        }
#pragma unroll
        for (int i = 0; i < NB; i++) {
            int krow = br + i * BROWS;
            pb[i] = *(const float4*)(B + (long long)(k0 + krow) * BN + bc);
        }
    };
    auto storeAB = [&](int d) {
#pragma unroll
        for (int i = 0; i < 2; i++) {
            As[d][ac + 0][ar + i * 64] = pa[i].x;
            As[d][ac + 1][ar + i * 64] = pa[i].y;
            As[d][ac + 2][ar + i * 64] = pa[i].z;
            As[d][ac + 3][ar + i * 64] = pa[i].w;
        }
#pragma unroll
        for (int i = 0; i < NB; i++)
            *(float4*)&Bs[d][br + i * BROWS][bc] = pb[i];
    };

    loadAB(0);
    storeAB(0);
    __syncthreads();
    int cur = 0;
#pragma unroll
    for (int s = 0; s < NSTEP; s++) {
        if (s + 1 < NSTEP) loadAB((s + 1) * BK);
#pragma unroll
        for (int k = 0; k < BK; k++) {
            float a[TM], b[TN];
#pragma unroll
            for (int i = 0; i < TM; i++) a[i] = As[cur][k][ty * TM + i];
#pragma unroll
            for (int j = 0; j < TN; j++) b[j] = Bs[cur][k][tx * TN + j];
#pragma unroll
            for (int i = 0; i < TM; i++)
#pragma unroll
                for (int j = 0; j < TN; j++) acc[i][j] += a[i] * b[j];
        }
        if (s + 1 < NSTEP) storeAB(cur ^ 1);
        __syncthreads();
        cur ^= 1;
    }

    float avs[TN], avd[TN];
#pragma unroll
    for (int j = 0; j < TN; j++) {
        avs[j] = att_s[tx * TN + j];
        avd[j] = att_d[tx * TN + j];
    }

    constexpr int STRIDE = L1 ? REC1_STRIDE : REC2_STRIDE;
    constexpr int LOFF   = L1 ? 256 : 128;

#pragma unroll
    for (int i = 0; i < TM; i++) {
        int row = m0 + ty * TM + i;
        float ps = 0.f, pd = 0.f;
#pragma unroll
        for (int j = 0; j < TN; j++) { ps += acc[i][j] * avs[j]; pd += acc[i][j] * avd[j]; }
        if (L1) {
            ps += __shfl_xor_sync(0xffffffffu, ps, 1);
            pd += __shfl_xor_sync(0xffffffffu, pd, 1);
            if (row < M && (tx & 1) == 0) {
                *(float*)(rec + (unsigned)row * STRIDE + LOFF + (tx >> 1) * 4) = ps * LOG2E;
                o_ad[row * H1 + (tx >> 1)] = pd * LOG2E;
            }
        } else {
#pragma unroll
            for (int o = 1; o < 16; o <<= 1) {
                ps += __shfl_xor_sync(0xffffffffu, ps, o);
                pd += __shfl_xor_sync(0xffffffffu, pd, o);
            }
            if (row < M && tx == 0) {
                *(float*)(rec + (unsigned)row * STRIDE + LOFF) = ps * LOG2E;
                o_ad[row] = pd * LOG2E;
            }
        }
        if (row < M) {
            half2 hh[TN / 2];
#pragma unroll
            for (int j = 0; j < TN; j += 2)
                hh[j / 2] = __floats2half2_rn(acc[i][j], acc[i][j + 1]);
            if (TN == 8)
                *(uint4*)(rec + (unsigned)row * STRIDE + tx * 16) = *(uint4*)hh;
            else
                *(uint2*)(rec + (unsigned)row * STRIDE + tx * 8) = *(uint2*)hh;
        }
    }
}

// ---------------- fused per-node aggregation --------------------------------
// Layer 1: warp per dst node; lane -> 4 cols; head = lane/4.
__global__ __launch_bounds__(256) void k_agg1(const float* __restrict__ b1, int N) {
    int g = blockIdx.x * blockDim.x + threadIdx.x;
    int node = g >> 5, lane = g & 31;
    if (node >= N) return;
    const int head = lane >> 2;
    const int deg  = min(g_deg[node], MAXDEG);
    const int* adj = g_adj + (node << 7);
    const float ad = g_ad1[node * H1 + head];
    const int fo = lane * 8;           // feature byte offset in record
    const int lo = 256 + head * 4;     // logit byte offset

    const unsigned char* nrec = g_rec1 + (unsigned)node * REC1_STRIDE;
    float w = wfun(*(const float*)(nrec + lo) + ad);
    float4 acc = make_float4(0.f, 0.f, 0.f, 0.f);
    acc4h(acc, w, *(const uint2*)(nrec + fo));
    float den = w;

    int i = 0;
    for (; i + 8 <= deg; i += 8) {
        int4 a0 = *(const int4*)(adj + i);
        int4 a1 = *(const int4*)(adj + i + 4);
        const unsigned char* r0 = g_rec1 + (unsigned)a0.x * REC1_STRIDE;
        const unsigned char* r1 = g_rec1 + (unsigned)a0.y * REC1_STRIDE;
        const unsigned char* r2 = g_rec1 + (unsigned)a0.z * REC1_STRIDE;
        const unsigned char* r3 = g_rec1 + (unsigned)a0.w * REC1_STRIDE;
        const unsigned char* r4 = g_rec1 + (unsigned)a1.x * REC1_STRIDE;
        const unsigned char* r5 = g_rec1 + (unsigned)a1.y * REC1_STRIDE;
        const unsigned char* r6 = g_rec1 + (unsigned)a1.z * REC1_STRIDE;
        const unsigned char* r7 = g_rec1 + (unsigned)a1.w * REC1_STRIDE;
        float l0 = *(const float*)(r0 + lo), l1 = *(const float*)(r1 + lo);
        float l2 = *(const float*)(r2 + lo), l3 = *(const float*)(r3 + lo);
        float l4 = *(const float*)(r4 + lo), l5 = *(const float*)(r5 + lo);
        float l6 = *(const float*)(r6 + lo), l7 = *(const float*)(r7 + lo);
        uint2 q0 = *(const uint2*)(r0 + fo), q1 = *(const uint2*)(r1 + fo);
        uint2 q2 = *(const uint2*)(r2 + fo), q3 = *(const uint2*)(r3 + fo);
        uint2 q4 = *(const uint2*)(r4 + fo), q5 = *(const uint2*)(r5 + fo);
        uint2 q6 = *(const uint2*)(r6 + fo), q7 = *(const uint2*)(r7 + fo);
        float w0 = wfun(l0 + ad), w1 = wfun(l1 + ad);
        float w2 = wfun(l2 + ad), w3 = wfun(l3 + ad);
        float w4 = wfun(l4 + ad), w5 = wfun(l5 + ad);
        float w6 = wfun(l6 + ad), w7 = wfun(l7 + ad);
        acc4h(acc, w0, q0); acc4h(acc, w1, q1);
        acc4h(acc, w2, q2); acc4h(acc, w3, q3);
        acc4h(acc, w4, q4); acc4h(acc, w5, q5);
        acc4h(acc, w6, q6); acc4h(acc, w7, q7);
        den += ((w0 + w1) + (w2 + w3)) + ((w4 + w5) + (w6 + w7));
    }
    for (; i + 4 <= deg; i += 4) {
        int4 a0 = *(const int4*)(adj + i);
        const unsigned char* r0 = g_rec1 + (unsigned)a0.x * REC1_STRIDE;
        const unsigned char* r1 = g_rec1 + (unsigned)a0.y * REC1_STRIDE;
        const unsigned char* r2 = g_rec1 + (unsigned)a0.z * REC1_STRIDE;
        const unsigned char* r3 = g_rec1 + (unsigned)a0.w * REC1_STRIDE;
        float l0 = *(const float*)(r0 + lo), l1 = *(const float*)(r1 + lo);
        float l2 = *(const float*)(r2 + lo), l3 = *(const float*)(r3 + lo);
        uint2 q0 = *(const uint2*)(r0 + fo), q1 = *(const uint2*)(r1 + fo);
        uint2 q2 = *(const uint2*)(r2 + fo), q3 = *(const uint2*)(r3 + fo);
        float w0 = wfun(l0 + ad), w1 = wfun(l1 + ad);
        float w2 = wfun(l2 + ad), w3 = wfun(l3 + ad);
        acc4h(acc, w0, q0); acc4h(acc, w1, q1);
        acc4h(acc, w2, q2); acc4h(acc, w3, q3);
        den += (w0 + w1) + (w2 + w3);
    }
    for (; i < deg; i++) {
        const unsigned char* r0 = g_rec1 + (unsigned)adj[i] * REC1_STRIDE;
        float w0 = wfun(*(const float*)(r0 + lo) + ad);
        acc4h(acc, w0, *(const uint2*)(r0 + fo));
        den += w0;
    }
    float inv = 1.f / den;
    float4 b = *(const float4*)&b1[lane * 4];
    float4 o = make_float4(acc.x * inv + b.x, acc.y * inv + b.y,
                           acc.z * inv + b.z, acc.w * inv + b.w);
    *(float4*)&g_h[((long long)node << 7) + lane * 4] = o;
}

// Layer 2: warp per dst node; lane -> 2 cols (1 half2); single head.
__global__ __launch_bounds__(256) void k_agg2(const float* __restrict__ b2,
                                              float* __restrict__ out, int N) {
    int g = blockIdx.x * blockDim.x + threadIdx.x;
    int node = g >> 5, lane = g & 31;
    if (node >= N) return;
    const int deg  = min(g_deg[node], MAXDEG);
    const int* adj = g_adj + (node << 7);
    const float ad = g_ad2[node];
    const int fo = lane * 4;
    const int lo = 128;

    const unsigned char* nrec = g_rec2 + (unsigned)node * REC2_STRIDE;
    float w = wfun(*(const float*)(nrec + lo) + ad);
    unsigned qs = *(const unsigned*)(nrec + fo);
    float2 fs = __half22float2(*reinterpret_cast<half2*>(&qs));
    float2 acc = make_float2(w * fs.x, w * fs.y);
    float den = w;

    int i = 0;
    for (; i + 8 <= deg; i += 8) {
        int4 a0 = *(const int4*)(adj + i);
        int4 a1 = *(const int4*)(adj + i + 4);
        const unsigned char* r0 = g_rec2 + (unsigned)a0.x * REC2_STRIDE;
        const unsigned char* r1 = g_rec2 + (unsigned)a0.y * REC2_STRIDE;
        const unsigned char* r2 = g_rec2 + (unsigned)a0.z * REC2_STRIDE;
        const unsigned char* r3 = g_rec2 + (unsigned)a0.w * REC2_STRIDE;
        const unsigned char* r4 = g_rec2 + (unsigned)a1.x * REC2_STRIDE;
        const unsigned char* r5 = g_rec2 + (unsigned)a1.y * REC2_STRIDE;
        const unsigned char* r6 = g_rec2 + (unsigned)a1.z * REC2_STRIDE;
        const unsigned char* r7 = g_rec2 + (unsigned)a1.w * REC2_STRIDE;
        float l0 = *(const float*)(r0 + lo), l1 = *(const float*)(r1 + lo);
        float l2 = *(const float*)(r2 + lo), l3 = *(const float*)(r3 + lo);
        float l4 = *(const float*)(r4 + lo), l5 = *(const float*)(r5 + lo);
        float l6 = *(const float*)(r6 + lo), l7 = *(const float*)(r7 + lo);
        unsigned q0 = *(const unsigned*)(r0 + fo), q1 = *(const unsigned*)(r1 + fo);
        unsigned q2 = *(const unsigned*)(r2 + fo), q3 = *(const unsigned*)(r3 + fo);
        unsigned q4 = *(const unsigned*)(r4 + fo), q5 = *(const unsigned*)(r5 + fo);
        unsigned q6 = *(const unsigned*)(r6 + fo), q7 = *(const unsigned*)(r7 + fo);
        float w0 = wfun(l0 + ad), w1 = wfun(l1 + ad);
        float w2 = wfun(l2 + ad), w3 = wfun(l3 + ad);
        float w4 = wfun(l4 + ad), w5 = wfun(l5 + ad);
        float w6 = wfun(l6 + ad), w7 = wfun(l7 + ad);
        float2 f;
        f = __half22float2(*reinterpret_cast<half2*>(&q0)); acc.x += w0 * f.x; acc.y += w0 * f.y;
        f = __half22float2(*reinterpret_cast<half2*>(&q1)); acc.x += w1 * f.x; acc.y += w1 * f.y;
        f = __half22float2(*reinterpret_cast<half2*>(&q2)); acc.x += w2 * f.x; acc.y += w2 * f.y;
        f = __half22float2(*reinterpret_cast<half2*>(&q3)); acc.x += w3 * f.x; acc.y += w3 * f.y;
        f = __half22float2(*reinterpret_cast<half2*>(&q4)); acc.x += w4 * f.x; acc.y += w4 * f.y;
        f = __half22float2(*reinterpret_cast<half2*>(&q5)); acc.x += w5 * f.x; acc.y += w5 * f.y;
        f = __half22float2(*reinterpret_cast<half2*>(&q6)); acc.x += w6 * f.x; acc.y += w6 * f.y;
        f = __half22float2(*reinterpret_cast<half2*>(&q7)); acc.x += w7 * f.x; acc.y += w7 * f.y;
        den += ((w0 + w1) + (w2 + w3)) + ((w4 + w5) + (w6 + w7));
    }
    for (; i + 4 <= deg; i += 4) {
        int4 a0 = *(const int4*)(adj + i);
        const unsigned char* r0 = g_rec2 + (unsigned)a0.x * REC2_STRIDE;
        const unsigned char* r1 = g_rec2 + (unsigned)a0.y * REC2_STRIDE;
        const unsigned char* r2 = g_rec2 + (unsigned)a0.z * REC2_STRIDE;
        const unsigned char* r3 = g_rec2 + (unsigned)a0.w * REC2_STRIDE;
        float l0 = *(const float*)(r0 + lo), l1 = *(const float*)(r1 + lo);
        float l2 = *(const float*)(r2 + lo), l3 = *(const float*)(r3 + lo);
        unsigned q0 = *(const unsigned*)(r0 + fo), q1 = *(const unsigned*)(r1 + fo);
        unsigned q2 = *(const unsigned*)(r2 + fo), q3 = *(const unsigned*)(r3 + fo);
        float w0 = wfun(l0 + ad), w1 = wfun(l1 + ad);
        float w2 = wfun(l2 + ad), w3 = wfun(l3 + ad);
        float2 f;
        f = __half22float2(*reinterpret_cast<half2*>(&q0)); acc.x += w0 * f.x; acc.y += w0 * f.y;
        f = __half22float2(*reinterpret_cast<half2*>(&q1)); acc.x += w1 * f.x; acc.y += w1 * f.y;
        f = __half22float2(*reinterpret_cast<half2*>(&q2)); acc.x += w2 * f.x; acc.y += w2 * f.y;
        f = __half22float2(*reinterpret_cast<half2*>(&q3)); acc.x += w3 * f.x; acc.y += w3 * f.y;
        den += (w0 + w1) + (w2 + w3);
    }
    for (; i < deg; i++) {
        const unsigned char* r0 = g_rec2 + (unsigned)adj[i] * REC2_STRIDE;
        float w0 = wfun(*(const float*)(r0 + lo) + ad);
        unsigned q0 = *(const unsigned*)(r0 + fo);
        float2 f = __half22float2(*reinterpret_cast<half2*>(&q0));
        acc.x += w0 * f.x; acc.y += w0 * f.y;
        den += w0;
    }
    float inv = 1.f / den;
    float2 b = *(const float2*)&b2[lane * 2];
    *(float2*)&out[((long long)node << 6) + lane * 2] =
        make_float2(acc.x * inv + b.x, acc.y * inv + b.y);
}

// ---------------- launch ----------------------------------------------------
extern "C" void kernel_launch(void* const* d_in, const int* in_sizes, int n_in,
                              void* d_out, int out_size) {
    const float* x   = (const float*)d_in[0];
    const int*   ei  = (const int*)d_in[1];
    const float* W1  = (const float*)d_in[2];
    const float* as1 = (const float*)d_in[3];
    const float* ad1 = (const float*)d_in[4];
    const float* b1  = (const float*)d_in[5];
    const float* W2  = (const float*)d_in[6];
    const float* as2 = (const float*)d_in[7];
    const float* ad2 = (const float*)d_in[8];
    const float* b2  = (const float*)d_in[9];
    float* out = (float*)d_out;

    const int N = in_sizes[0] / F_IN;
    const int E = in_sizes[1] / 2;

    unsigned char *p_rec1, *p_rec2;
    float *p_h, *p_ad1, *p_ad2;
    cudaGetSymbolAddress((void**)&p_rec1, g_rec1);
    cudaGetSymbolAddress((void**)&p_rec2, g_rec2);
    cudaGetSymbolAddress((void**)&p_h,    g_h);
    cudaGetSymbolAddress((void**)&p_ad1,  g_ad1);
    cudaGetSymbolAddress((void**)&p_ad2,  g_ad2);

    k_zero<<<(N + 255) / 256, 256>>>(N);
    k_scatter<<<(E / 4 + 255) / 256, 256>>>(ei, E);
    k_sgemm<128, 8, false, true><<<(N + 127) / 128, 256>>>(x, W1, p_rec1, as1, ad1, p_ad1, N);
    k_agg1<<<(N * 32 + 255) / 256, 256>>>(b1, N);
    k_sgemm<64, 4, true, false><<<(N + 127) / 128, 256>>>(p_h, W2, p_rec2, as2, ad2, p_ad2, N);
    k_agg2<<<(N * 32 + 255) / 256, 256>>>(b2, out, N);
}